// round 7
// baseline (speedup 1.0000x reference)
#include <cuda_runtime.h>
#include <math.h>
#include <float.h>

// ---------------- problem constants ----------------
#define NIMG 4
#define H 128
#define W 128
#define P 11
#define KSEL 16
#define WIN 65
#define V 32
#define S 3
#define HREF 40
#define WREF 40
#define LGRP (HREF*WREF)
#define WP 118              // H - P + 1
#define NPIX (H*W)
#define NPATCH (P*P)
#define NOFF 65
#define NSLC 6              // oy slices per (n,gh)
#define NQ 6                // ox interleave in phase 2
#define CSW 129             // padded CS row width
#define E_REG 30.25f
#define DE_REG 151.25f

// ---------------- device scratch ----------------
__device__ float g_pv[NIMG * HREF * NSLC * WREF * KSEL];
__device__ int   g_pi[NIMG * HREF * NSLC * WREF * KSEL];
__device__ int   g_ind[NIMG * LGRP * KSEL];
__device__ float g_num[NIMG * NPIX];
__device__ float g_den[NIMG * NPIX];

// ---------------- zero accumulators ----------------
__global__ void zero_kernel() {
    int i = blockIdx.x * blockDim.x + threadIdx.x;
    if (i < NIMG * NPIX) { g_num[i] = 0.f; g_den[i] = 0.f; }
}

// ---------------- fused block matching ----------------
// grid: NIMG*HREF*NSLC CTAs, 256 threads. Per oy: two ox-halves, each
// phase1 (column sums into CS) + phase2 (horizontal sums + register top-16).
// BR double-buffered; next-oy staging overlapped with phase2 of half 1.
__global__ __launch_bounds__(256) void bm_kernel(const float* __restrict__ y) {
    __shared__ float SM[7680];               // 30.7KB blob
    float* CS = SM;                          // [33][129] = 4257 floats
    float* BR = SM + 33 * CSW;               // [2][11][128] = 2816 floats

    const int blk = blockIdx.x;
    const int s   = blk % NSLC;
    const int gid = blk / NSLC;
    const int gh  = gid % HREF;
    const int n   = gid / HREF;
    const int t   = threadIdx.x;
    const int c   = t & 127;
    const float* img = y + n * NPIX;

    // reference band rows in registers
    float a[P];
#pragma unroll
    for (int r = 0; r < P; r++) a[r] = __ldg(&img[(3 * gh + r) * W + c]);

    // oy slice
    const int oylo = max(-V, -3 * gh);
    const int oyhi = min(V, (H - P) - 3 * gh);
    const int cnt  = oyhi - oylo + 1;
    const int s0   = oylo + (cnt * s) / NSLC;
    const int s1   = oylo + (cnt * (s + 1)) / NSLC;

    const int gw = t % WREF;
    const int q  = t / WREF;                 // 0..5 for t<240
    float vals[KSEL];
    int   idxs[KSEL];
#pragma unroll
    for (int j = 0; j < KSEL; j++) { vals[j] = FLT_MAX; idxs[j] = 0; }
    float cmax = FLT_MAX; int am = 0;

    // stage BR buffer 0 for oy = s0
    for (int i = t; i < P * W; i += 256) {
        int r = i >> 7, cc = i & 127;
        int rs = min(max(3 * gh + r + s0, 0), H - 1);
        BR[r * W + cc] = __ldg(&img[rs * W + cc]);
    }
    __syncthreads();

    for (int oy = s0; oy < s1; oy++) {
        const int cur = (oy - s0) & 1;
        const float* brc = BR + cur * P * W;

#pragma unroll
        for (int half = 0; half < 2; half++) {
            const int oxbase = half * 33;
            const int cnt_h  = half ? 32 : 33;

            // ---- phase 1: column sums ----
            for (int oxl = (t >> 7); oxl < cnt_h; oxl += 2) {
                int ox = oxbase + oxl - V;
                int cb = min(max(c + ox, 0), W - 1);
                float acc = 0.f;
#pragma unroll
                for (int r = 0; r < P; r++) {
                    float d = a[r] - brc[r * W + cb];
                    acc = fmaf(d, d, acc);
                }
                CS[oxl * CSW + c] = acc;
            }
            __syncthreads();

            // ---- stage next oy's BR (overlapped, half 1 only) ----
            if (half == 1 && oy + 1 < s1) {
                const int nxt = cur ^ 1;
                for (int i = t; i < P * W; i += 256) {
                    int r = i >> 7, cc = i & 127;
                    int rs = min(max(3 * gh + r + oy + 1, 0), H - 1);
                    BR[(nxt * P + r) * W + cc] = __ldg(&img[rs * W + cc]);
                }
            }

            // ---- phase 2: horizontal 11-sums + top-16 ----
            if (t < WREF * NQ) {
                for (int oxl = q; oxl < cnt_h; oxl += NQ) {
                    int oxg = oxbase + oxl;
                    int ox  = oxg - V;
                    int ccand = 3 * gw + ox;
                    if ((unsigned)ccand > (unsigned)(W - P)) continue;
                    const float* row = &CS[oxl * CSW + 3 * gw];
                    float d = 0.f;
#pragma unroll
                    for (int b = 0; b < P; b++) d += row[b];
                    if (oy == 0 && ox == 0) d = -FLT_MAX;
                    if (d < cmax) {
                        vals[am] = d; idxs[am] = (oy + V) * NOFF + oxg;
                        cmax = vals[0]; am = 0;
#pragma unroll
                        for (int j = 1; j < KSEL; j++)
                            if (vals[j] > cmax) { cmax = vals[j]; am = j; }
                    }
                }
            }
            __syncthreads();
        }
    }

    // ---- in-CTA merge: 6 q-partials -> 16 per gw (overlay SM) ----
    float* MV = SM;                          // 240*16 floats
    int*   MI = (int*)(SM + WREF * NQ * KSEL);
    if (t < WREF * NQ) {
#pragma unroll
        for (int j = 0; j < KSEL; j++) {
            MV[(gw * NQ + q) * KSEL + j] = vals[j];
            MI[(gw * NQ + q) * KSEL + j] = idxs[j];
        }
    }
    __syncthreads();
    if (t < WREF) {
        float* mv = &MV[t * NQ * KSEL];
        int*   mi = &MI[t * NQ * KSEL];
        float* pv = &g_pv[((size_t)blk * WREF + t) * KSEL];
        int*   pi = &g_pi[((size_t)blk * WREF + t) * KSEL];
        for (int sel = 0; sel < KSEL; sel++) {
            float bv = FLT_MAX; int bs = 0;
            for (int m = 0; m < NQ * KSEL; m++) {
                float v = mv[m];
                if (v < bv) { bv = v; bs = m; }
            }
            pv[sel] = bv;
            pi[sel] = mi[bs];
            mv[bs] = FLT_MAX;
        }
    }
}

// ---------------- cross-slice merge: 6x16 -> final 16 ----------------
__global__ __launch_bounds__(64) void bm_merge_kernel() {
    const int gh = blockIdx.x % HREF;
    const int n  = blockIdx.x / HREF;
    const int gw = threadIdx.x;
    if (gw >= WREF) return;

    const int gbase = (n * HREF + gh) * NSLC;

    float vals[KSEL];
    int   idxs[KSEL];
#pragma unroll
    for (int j = 0; j < KSEL; j++) { vals[j] = FLT_MAX; idxs[j] = 0; }
    float cmax = FLT_MAX; int am = 0;

    for (int sl = 0; sl < NSLC; sl++) {
        const float* pv = &g_pv[((size_t)(gbase + sl) * WREF + gw) * KSEL];
        const int*   pi = &g_pi[((size_t)(gbase + sl) * WREF + gw) * KSEL];
#pragma unroll
        for (int m = 0; m < KSEL; m++) {
            float v = pv[m];
            if (v < cmax) {
                vals[am] = v; idxs[am] = pi[m];
                cmax = vals[0]; am = 0;
#pragma unroll
                for (int j = 1; j < KSEL; j++)
                    if (vals[j] > cmax) { cmax = vals[j]; am = j; }
            }
        }
    }

    int* out = &g_ind[((n * LGRP) + gh * WREF + gw) * KSEL];
#pragma unroll
    for (int j = 0; j < KSEL; j++) {
        int o = idxs[j];
        int oy = o / NOFF - V, ox = o % NOFF - V;
        out[j] = (3 * gh + oy) * WP + (3 * gw + ox);
    }
}

// ---------------- gather + denoise + scatter ----------------
__global__ __launch_bounds__(128) void denoise_kernel(const float* __restrict__ y) {
    __shared__ float Ys[KSEL][NPATCH + 3];
    __shared__ float Qs[KSEL][KSEL + 1];
    __shared__ float Qi[KSEL][KSEL + 1];
    __shared__ float Th[KSEL][KSEL + 1];
    __shared__ float wgt[KSEL];
    __shared__ float q1[KSEL];
    __shared__ float q2s;
    __shared__ int   pr[KSEL], pc[KSEL];

    const int g = blockIdx.x;
    const int n = g / LGRP;
    const int tid = threadIdx.x;
    const float* img = y + n * NPIX;

    if (tid < KSEL) {
        int idx = g_ind[g * KSEL + tid];
        pr[tid] = idx / WP;
        pc[tid] = idx % WP;
    }
    __syncthreads();

    for (int t = tid; t < KSEL * NPATCH; t += 128) {
        int i = t / NPATCH, e = t % NPATCH;
        int a = e / P, b = e % P;
        Ys[i][e] = img[(pr[i] + a) * W + pc[i] + b];
    }
    __syncthreads();

    // Q = Y Y^T + E I : upper triangle only (136 pairs), mirror
    for (int tt = tid; tt < 136; tt += 128) {
        int i = 0, rem = tt;
        while (rem >= KSEL - i) { rem -= KSEL - i; i++; }
        int j = i + rem;
        float s = 0.f;
        for (int e = 0; e < NPATCH; e++) s += Ys[i][e] * Ys[j][e];
        if (i == j) s += E_REG;
        Qs[i][j] = s;
        Qs[j][i] = s;
    }
    __syncthreads();

    if (tid < 32) {
        int lane = tid;
        for (int j = 0; j < KSEL; j++) {
            if (lane == 0) Qs[j][j] = sqrtf(Qs[j][j]);
            __syncwarp();
            float dj = Qs[j][j];
            if (lane > j && lane < KSEL) Qs[lane][j] /= dj;
            __syncwarp();
            if (lane > j && lane < KSEL) {
                float lij = Qs[lane][j];
                for (int m = j + 1; m <= lane; m++) Qs[lane][m] -= lij * Qs[m][j];
            }
            __syncwarp();
        }
        if (lane < KSEL) {
            float z[KSEL];
            for (int i = 0; i < KSEL; i++) {
                float s = (i == lane) ? 1.f : 0.f;
                for (int j = 0; j < i; j++) s -= Qs[i][j] * z[j];
                z[i] = s / Qs[i][i];
            }
            for (int i = KSEL - 1; i >= 0; i--) {
                float s = z[i];
                for (int j = i + 1; j < KSEL; j++) s -= Qs[j][i] * z[j];
                z[i] = s / Qs[i][i];
            }
            for (int i = 0; i < KSEL; i++) Qi[i][lane] = z[i];
        }
    }
    __syncthreads();

    if (tid < KSEL) {
        float s = 0.f;
        for (int j = 0; j < KSEL; j++) s += Qi[tid][j];
        q1[tid] = s;
    }
    __syncthreads();
    if (tid == 0) {
        float s = 0.f;
        for (int i = 0; i < KSEL; i++) s += q1[i];
        q2s = s;
    }
    __syncthreads();
    for (int t = tid; t < KSEL * KSEL; t += 128) {
        int i = t / KSEL, j = t % KSEL;
        Th[i][j] = ((i == j) ? 1.f : 0.f) - (Qi[i][j] - q1[i] * q1[j] / q2s) * DE_REG;
    }
    __syncthreads();
    if (tid < KSEL) {
        float s = 0.f;
        for (int j = 0; j < KSEL; j++) s += Th[tid][j] * Th[tid][j];
        s = fminf(fmaxf(s, 1.f / (float)KSEL), 1.f);
        wgt[tid] = 1.f / s;
    }
    __syncthreads();

    float* numI = g_num + n * NPIX;
    float* denI = g_den + n * NPIX;
    for (int t = tid; t < KSEL * NPATCH; t += 128) {
        int i = t / NPATCH, e = t % NPATCH;
        float s = 0.f;
#pragma unroll
        for (int j = 0; j < KSEL; j++) s += Th[i][j] * Ys[j][e];
        float wv = wgt[i];
        int a = e / P, b = e % P;
        int pix = (pr[i] + a) * W + pc[i] + b;
        atomicAdd(&numI[pix], s * wv);
        atomicAdd(&denI[pix], wv);
    }
}

// ---------------- final divide ----------------
__global__ void div_kernel(float* __restrict__ out) {
    int i = blockIdx.x * blockDim.x + threadIdx.x;
    if (i < NIMG * NPIX) out[i] = g_num[i] / g_den[i];
}

extern "C" void kernel_launch(void* const* d_in, const int* in_sizes, int n_in,
                              void* d_out, int out_size) {
    const float* y = (const float*)d_in[0];
    float* out = (float*)d_out;

    zero_kernel<<<(NIMG * NPIX + 255) / 256, 256>>>();

    bm_kernel<<<NIMG * HREF * NSLC, 256>>>(y);

    bm_merge_kernel<<<NIMG * HREF, 64>>>();

    denoise_kernel<<<NIMG * LGRP, 128>>>(y);

    div_kernel<<<(NIMG * NPIX + 255) / 256, 256>>>(out);
}